// round 16
// baseline (speedup 1.0000x reference)
#include <cuda_runtime.h>
#include <cuda_bf16.h>
#include <math.h>
#include <stdint.h>

#define Bv 4
#define Sv 2048
#define Fv 128
#define Hv 4
#define Dv 128
#define HDv 512
#define OUTv 128
#define BHv 16
#define NSv (BHv*Sv)
#define NEG 0.01f

// ---- device scratch ----
__device__ float g_hp[NSv*Dv];          // fp32 [bh][s][d]
__device__ float g_e1[NSv];
__device__ float g_e2[NSv];
__device__ float g_An[NSv];
__device__ float g_Bn[NSv];
__device__ float g_th[NSv];
__device__ float g_E2p[NSv];
__device__ float g_E2n[NSv];
__device__ uint32_t g_loi[NSv];         // sorted (lo<<11 | i) per bh
__device__ int   g_perm[NSv];
__device__ float g_sEp[NSv];
__device__ float g_sEn[NSv];
__device__ int   g_masked[Bv*Sv];
__device__ float g_segsum[BHv*2*8*Dv];  // [(bh<<4)|(dir<<3)|seg][d], dir1=Ep dir0=En
__device__ __nv_bfloat16 g_ctxb_hi[Bv*Sv*HDv];
__device__ __nv_bfloat16 g_ctxb_lo[Bv*Sv*HDv];
__device__ __nv_bfloat16 g_wb_hi[OUTv*HDv];
__device__ __nv_bfloat16 g_wb_lo[OUTv*HDv];

__device__ __forceinline__ uint32_t smem_u32(const void* p) {
    uint32_t a;
    asm("{ .reg .u64 t; cvta.to.shared.u64 t, %1; cvt.u32.u64 %0, t; }" : "=r"(a) : "l"(p));
    return a;
}
#define LDMX4(r0,r1,r2,r3,addr) \
    asm volatile("ldmatrix.sync.aligned.m8n8.x4.shared.b16 {%0,%1,%2,%3}, [%4];" \
        : "=r"(r0),"=r"(r1),"=r"(r2),"=r"(r3) : "r"(addr))
#define MMA16816(c,a0,a1,a2,a3,b0,b1) \
    asm volatile("mma.sync.aligned.m16n8k16.row.col.f32.bf16.bf16.f32 " \
        "{%0,%1,%2,%3}, {%4,%5,%6,%7}, {%8,%9}, {%0,%1,%2,%3};" \
        : "+f"((c)[0]),"+f"((c)[1]),"+f"((c)[2]),"+f"((c)[3]) \
        : "r"(a0),"r"(a1),"r"(a2),"r"(a3), "r"(b0),"r"(b1))
#define CP16(dst, src) \
    asm volatile("cp.async.cg.shared.global [%0], [%1], 16;" :: "r"(dst), "l"(src) : "memory")
#define CP_COMMIT() asm volatile("cp.async.commit_group;" ::: "memory")
#define CP_WAIT1()  asm volatile("cp.async.wait_group 1;" ::: "memory")
#define CP_WAIT0()  asm volatile("cp.async.wait_group 0;" ::: "memory")

__device__ __forceinline__ uint32_t pack_hi2(float a, float b) {
    __nv_bfloat16 ha = __float2bfloat16_rn(a), hb = __float2bfloat16_rn(b);
    return ((uint32_t)__bfloat16_as_ushort(hb) << 16) | __bfloat16_as_ushort(ha);
}
__device__ __forceinline__ uint32_t pack_lo2(float a, float b) {
    __nv_bfloat16 ha = __float2bfloat16_rn(a), hb = __float2bfloat16_rn(b);
    float ra = a - __bfloat162float(ha), rb = b - __bfloat162float(hb);
    __nv_bfloat16 la = __float2bfloat16_rn(ra), lb = __float2bfloat16_rn(rb);
    return ((uint32_t)__bfloat16_as_ushort(lb) << 16) | __bfloat16_as_ushort(la);
}

extern __shared__ __align__(128) unsigned char dynsmem[];

// ---------------------------------------------------------------
// K0: decode mask buffer
// ---------------------------------------------------------------
__global__ void k_mask(const void* mraw) {
    __shared__ int ssum[256];
    __shared__ int fmt;
    const unsigned char* mb = (const unsigned char*)mraw;
    int tid = threadIdx.x;
    int s = 0;
    for (int i = tid; i < Bv*Sv; i += 256) s += mb[i];
    ssum[tid] = s;
    __syncthreads();
    for (int st = 128; st > 0; st >>= 1) {
        if (tid < st) ssum[tid] += ssum[tid + st];
        __syncthreads();
    }
    if (tid == 0) fmt = (ssum[0] > (Bv*Sv*5/16)) ? 1 : 0;
    __syncthreads();
    if (fmt) {
        for (int i = tid; i < Bv*Sv; i += 256) g_masked[i] = (mb[i] != 0);
    } else {
        const int* mi = (const int*)mraw;
        for (int i = tid; i < Bv*Sv; i += 256) g_masked[i] = (mi[i] != 0);
    }
}

// ---------------------------------------------------------------
// K0b: convert out_w to bf16 hi/lo (side stream)
// ---------------------------------------------------------------
__global__ void k_wcvt(const float* __restrict__ W) {
    int i = blockIdx.x * 256 + threadIdx.x;
    float4 v = *(const float4*)(W + (size_t)i*4);
    *(uint2*)(g_wb_hi + (size_t)i*4) = make_uint2(pack_hi2(v.x,v.y), pack_hi2(v.z,v.w));
    *(uint2*)(g_wb_lo + (size_t)i*4) = make_uint2(pack_lo2(v.x,v.y), pack_lo2(v.z,v.w));
}

// ---------------------------------------------------------------
// K1: hp GEMM + fused e1/e2 (K-halved pipelined prologue, R15 form)
// ---------------------------------------------------------------
#define G1_LDK 136
#define G1_T  (128*G1_LDK*2)
#define G1_AH 0u
#define G1_AL ((uint32_t)G1_T)
#define G1_BH ((uint32_t)(2*G1_T))
#define G1_BL ((uint32_t)(3*G1_T))
#define G1_RED ((uint32_t)(4*G1_T))
#define G1_SA  ((uint32_t)(4*G1_T + 4096))
#define G1_SMEM (4*G1_T + 4096 + 1024)

__device__ __forceinline__ void g1_convert_half(const float* __restrict__ A,
                                                const float* __restrict__ W,
                                                int m0, int n0, int half, int tid) {
    const int cbase = half * 64;
    #pragma unroll
    for (int t = 0; t < 4; t++) {
        int idx = tid + t*512;
        int r = idx >> 4, c4 = ((idx & 15) << 2) + cbase;
        float4 v = *(const float4*)(A + (size_t)(m0+r)*Fv + c4);
        uint32_t boff = (uint32_t)(r*G1_LDK + c4) * 2;
        *(uint2*)(dynsmem + G1_AH + boff) = make_uint2(pack_hi2(v.x,v.y), pack_hi2(v.z,v.w));
        *(uint2*)(dynsmem + G1_AL + boff) = make_uint2(pack_lo2(v.x,v.y), pack_lo2(v.z,v.w));
    }
    #pragma unroll
    for (int t = 0; t < 4; t++) {
        int idx = tid + t*512;
        int r = idx >> 4, c4 = ((idx & 15) << 2) + cbase;
        float4 v = *(const float4*)(W + (size_t)(n0+r)*Fv + c4);
        uint32_t boff = (uint32_t)(r*G1_LDK + c4) * 2;
        *(uint2*)(dynsmem + G1_BH + boff) = make_uint2(pack_hi2(v.x,v.y), pack_hi2(v.z,v.w));
        *(uint2*)(dynsmem + G1_BL + boff) = make_uint2(pack_lo2(v.x,v.y), pack_lo2(v.z,v.w));
    }
}

__global__ __launch_bounds__(512, 1) void k_gemm1t(const float* __restrict__ A,
                                                   const float* __restrict__ W,
                                                   const float* __restrict__ bias,
                                                   const float* __restrict__ aw) {
    const int m0 = blockIdx.x * 128;
    const int n0 = blockIdx.y * 128;
    const int tid = threadIdx.x;
    const int w = tid >> 5, lane = tid & 31;
    const uint32_t sb = smem_u32(dynsmem);

    if (tid < 256) ((float*)(dynsmem + G1_SA))[tid] = aw[tid];

    g1_convert_half(A, W, m0, n0, 0, tid);
    __syncthreads();

    const int wm = w >> 2, wn = w & 3;
    const uint32_t arow = (uint32_t)((wm*32 + (lane & 15))*G1_LDK + (lane >> 4)*8) * 2;
    const uint32_t brow = (uint32_t)(((lane & 7) + ((lane >> 4) << 3))*G1_LDK
                                     + (((lane >> 3) & 1)*8)) * 2;
    float c[2][4][4] = {};

    #pragma unroll
    for (int half = 0; half < 2; half++) {
        if (half == 0) g1_convert_half(A, W, m0, n0, 1, tid);
        #pragma unroll
        for (int ks = half*4; ks < half*4 + 4; ks++) {
            uint32_t bhf[2][4], blf[2][4];
            #pragma unroll
            for (int np = 0; np < 2; np++) {
                uint32_t bt = (uint32_t)((wn*32 + np*16)*G1_LDK)*2 + (uint32_t)(ks*16)*2;
                LDMX4(bhf[np][0],bhf[np][1],bhf[np][2],bhf[np][3], sb + G1_BH + brow + bt);
                LDMX4(blf[np][0],blf[np][1],blf[np][2],blf[np][3], sb + G1_BL + brow + bt);
            }
            #pragma unroll
            for (int mt = 0; mt < 2; mt++) {
                uint32_t at = (uint32_t)(mt*16*G1_LDK)*2 + (uint32_t)(ks*16)*2;
                uint32_t ah0,ah1,ah2,ah3, al0,al1,al2,al3;
                LDMX4(ah0,ah1,ah2,ah3, sb + G1_AH + arow + at);
                LDMX4(al0,al1,al2,al3, sb + G1_AL + arow + at);
                #pragma unroll
                for (int np = 0; np < 2; np++) {
                    MMA16816(c[mt][np*2],   ah0,ah1,ah2,ah3, bhf[np][0],bhf[np][1]);
                    MMA16816(c[mt][np*2],   al0,al1,al2,al3, bhf[np][0],bhf[np][1]);
                    MMA16816(c[mt][np*2],   ah0,ah1,ah2,ah3, blf[np][0],blf[np][1]);
                    MMA16816(c[mt][np*2+1], ah0,ah1,ah2,ah3, bhf[np][2],bhf[np][3]);
                    MMA16816(c[mt][np*2+1], al0,al1,al2,al3, bhf[np][2],bhf[np][3]);
                    MMA16816(c[mt][np*2+1], ah0,ah1,ah2,ah3, blf[np][2],blf[np][3]);
                }
            }
        }
        if (half == 0) __syncthreads();
    }

    const int bb = m0 >> 11, s0 = m0 & (Sv-1), hh = n0 >> 7;
    const int bh = bb*Hv + hh;
    const int g = lane >> 2, tg = lane & 3;
    float* red = (float*)(dynsmem + G1_RED);
    const float* sa1 = (const float*)(dynsmem + G1_SA);
    const float* sa2 = sa1 + 128;

    float pe1[2][2] = {}, pe2[2][2] = {};
    #pragma unroll
    for (int mt = 0; mt < 2; mt++) {
        #pragma unroll
        for (int nt = 0; nt < 4; nt++) {
            int d = wn*32 + nt*8 + tg*2;
            float b0 = bias[n0 + d], b1 = bias[n0 + d + 1];
            float a10 = sa1[d], a11 = sa1[d+1];
            float a20 = sa2[d], a21 = sa2[d+1];
            #pragma unroll
            for (int half = 0; half < 2; half++) {
                int r = wm*32 + mt*16 + half*8 + g;
                float v0 = c[mt][nt][half*2]   + b0;
                float v1 = c[mt][nt][half*2+1] + b1;
                *(float2*)(g_hp + ((size_t)bh*Sv + s0 + r)*Dv + d) = make_float2(v0, v1);
                pe1[mt][half] += v0*a10 + v1*a11;
                pe2[mt][half] += v0*a20 + v1*a21;
            }
        }
    }
    #pragma unroll
    for (int mt = 0; mt < 2; mt++) {
        #pragma unroll
        for (int half = 0; half < 2; half++) {
            float e1 = pe1[mt][half], e2 = pe2[mt][half];
            e1 += __shfl_xor_sync(0xffffffffu, e1, 1);
            e1 += __shfl_xor_sync(0xffffffffu, e1, 2);
            e2 += __shfl_xor_sync(0xffffffffu, e2, 1);
            e2 += __shfl_xor_sync(0xffffffffu, e2, 2);
            if (tg == 0) {
                int r = wm*32 + mt*16 + half*8 + g;
                red[(r*4 + wn)*2 + 0] = e1;
                red[(r*4 + wn)*2 + 1] = e2;
            }
        }
    }
    __syncthreads();
    if (tid < 128) {
        int r = tid;
        float e1 = red[(r*4+0)*2] + red[(r*4+1)*2] + red[(r*4+2)*2] + red[(r*4+3)*2];
        float e2 = red[(r*4+0)*2+1] + red[(r*4+1)*2+1] + red[(r*4+2)*2+1] + red[(r*4+3)*2+1];
        int s = s0 + r;
        int row = bh*Sv + s;
        g_e1[row] = e1;
        g_e2[row] = e2;
        int msk = g_masked[bb*Sv + s];
        g_E2p[row] = msk ? 0.f : expf(e2);
        g_E2n[row] = msk ? 0.f : expf(NEG*e2);
    }
}

// ---------------------------------------------------------------
// K2: per (b,h) softmax prep. Sort #1 (u32 packed e2-key) -> exp
// tables/scans/bsearch -> Sort #2 (lo<<11|i) -> g_loi.
// ---------------------------------------------------------------
#define P_SKEY 0u
#define P_KEYF 16384u
#define P_V1   24576u
#define P_V2   32768u
#define P_PREN 40960u
#define P_SUFP 49408u
#define P_CH1  57856u
#define P_CH2  58112u
#define PREP_SMEM 58880

__device__ __forceinline__ uint32_t f2sort(float f) {
    uint32_t u = __float_as_uint(f);
    return (u & 0x80000000u) ? ~u : (u | 0x80000000u);
}
__device__ __forceinline__ uint32_t bsel32(uint32_t a, uint32_t p, bool up, bool lower) {
    uint32_t mn = a < p ? a : p;
    uint32_t mx = a < p ? p : a;
    return (up == lower) ? mn : mx;
}

__device__ __forceinline__ void bitonic2(uint32_t& r0, uint32_t& r1,
                                         uint32_t* skey, int tid) {
    for (int k = 2; k <= Sv; k <<= 1) {
        const bool up = (((2*tid) & k) == 0);
        for (int j = k >> 1; j > 0; j >>= 1) {
            if (j == 1) {
                if ((r0 > r1) == up) { uint32_t t = r0; r0 = r1; r1 = t; }
            } else if (j <= 32) {
                int m = j >> 1;
                uint32_t p0 = __shfl_xor_sync(0xffffffffu, r0, m);
                uint32_t p1 = __shfl_xor_sync(0xffffffffu, r1, m);
                bool lower = ((tid & m) == 0);
                r0 = bsel32(r0, p0, up, lower);
                r1 = bsel32(r1, p1, up, lower);
            } else {
                __syncthreads();
                skey[2*tid] = r0; skey[2*tid+1] = r1;
                __syncthreads();
                int pt = tid ^ (j >> 1);
                uint32_t p0 = skey[2*pt];
                uint32_t p1 = skey[2*pt+1];
                bool lower = ((tid & (j >> 1)) == 0);
                r0 = bsel32(r0, p0, up, lower);
                r1 = bsel32(r1, p1, up, lower);
            }
        }
    }
}

__global__ __launch_bounds__(1024) void k_prep(const float* __restrict__ ab_p) {
    uint32_t* skey = (uint32_t*)(dynsmem + P_SKEY);
    float* keyf = (float*)(dynsmem + P_KEYF);
    float* v1   = (float*)(dynsmem + P_V1);
    float* v2   = (float*)(dynsmem + P_V2);
    float* pren = (float*)(dynsmem + P_PREN);
    float* sufp = (float*)(dynsmem + P_SUFP);
    float* ch1  = (float*)(dynsmem + P_CH1);
    float* ch2  = (float*)(dynsmem + P_CH2);

    const int bh = blockIdx.x;
    const int b  = bh >> 2;
    const int tid = threadIdx.x;
    const float ab = ab_p[0];

    uint32_t r0, r1;
    {
        int j0 = 2*tid, j1 = 2*tid + 1;
        float e20 = g_e2[bh*Sv + j0], e21 = g_e2[bh*Sv + j1];
        float k0 = g_masked[b*Sv + j0] ? -1e30f : e20;
        float k1 = g_masked[b*Sv + j1] ? -1e30f : e21;
        r0 = (f2sort(k0) & 0xFFFFF800u) | (uint32_t)j0;
        r1 = (f2sort(k1) & 0xFFFFF800u) | (uint32_t)j1;
    }
    bitonic2(r0, r1, skey, tid);
    __syncthreads();
    skey[2*tid] = r0; skey[2*tid+1] = r1;
    __syncthreads();

    for (int n = tid; n < Sv; n += 1024) {
        int jj = (int)(skey[n] & 2047u);
        int msk = g_masked[b*Sv + jj];
        float kf = msk ? -1e30f : g_e2[bh*Sv + jj];
        float ep = expf(kf), en = expf(NEG*kf);
        keyf[n] = kf; v1[n] = ep; v2[n] = en;
        g_perm[bh*Sv + n] = jj;
        g_sEp[bh*Sv + n] = ep;
        g_sEn[bh*Sv + n] = en;
    }
    __syncthreads();

    const float M2 = keyf[Sv-1];

    if (tid < 64) {
        int base = tid * 32;
        float s1 = 0.f, s2 = 0.f;
        for (int t = 0; t < 32; t++) { s1 += v1[base+t]; s2 += v2[base+t]; }
        ch1[tid] = s1; ch2[tid] = s2;
    }
    __syncthreads();
    if (tid == 0) {
        float r = 0.f;
        for (int c = 0; c < 64; c++) { float t = ch2[c]; ch2[c] = r; r += t; }
        pren[Sv] = r;
        r = 0.f;
        for (int c = 63; c >= 0; c--) { float t = ch1[c]; ch1[c] = r; r += t; }
    }
    __syncthreads();
    if (tid < 64) {
        int base = tid * 32;
        float run = ch2[tid];
        for (int t = 0; t < 32; t++) { pren[base+t] = run; run += v2[base+t]; }
        float runs = ch1[tid];
        for (int t = 31; t >= 0; t--) { runs += v1[base+t]; sufp[base+t] = runs; }
    }
    if (tid == 0) sufp[Sv] = 0.f;
    __syncthreads();

    // row phase: An/Bn/th + build (lo<<11|i) keys in skey (by row index)
    for (int i = tid; i < Sv; i += 1024) {
        float e1 = g_e1[bh*Sv + i];
        float eb = e1 + ab;
        float pre = eb + M2;
        float m = (pre > 0.f) ? pre : NEG*pre;
        float th = -eb;
        float A  = expf(eb - m);
        float Bc = expf(NEG*eb - m);
        int lo = 0, hi = Sv;
        while (lo < hi) {
            int mid = (lo + hi) >> 1;
            if (keyf[mid] <= th) lo = mid + 1; else hi = mid;
        }
        float rowsum = A*sufp[lo] + Bc*pren[lo];
        float inv = 1.0f / rowsum;
        g_An[bh*Sv + i] = A * inv;
        g_Bn[bh*Sv + i] = Bc * inv;
        g_th[bh*Sv + i] = th;
        skey[i] = ((uint32_t)lo << 11) | (uint32_t)i;
    }
    __syncthreads();

    // sort #2: group rows by rank
    uint32_t q0 = skey[2*tid], q1 = skey[2*tid+1];
    bitonic2(q0, q1, skey, tid);
    g_loi[bh*Sv + 2*tid]     = q0;
    g_loi[bh*Sv + 2*tid + 1] = q1;
}

// ---------------------------------------------------------------
// K3a: segment sums (dir-separated, unchanged R13 form)
// ---------------------------------------------------------------
__global__ __launch_bounds__(128) void k_scan1() {
    __shared__ float wv[256];
    __shared__ int pm[256];
    const int blk = blockIdx.x;
    const int seg = blk & 7;
    const int dir = (blk >> 3) & 1;
    const int bh  = blk >> 4;
    const int d = threadIdx.x;
    const int n0 = seg * 256;
    const float* src = dir ? (g_sEp + bh*Sv) : (g_sEn + bh*Sv);
    for (int t = d; t < 256; t += 128) {
        wv[t] = src[n0 + t];
        pm[t] = g_perm[bh*Sv + n0 + t];
    }
    __syncthreads();
    const float* hp = g_hp + (size_t)bh*Sv*Dv;
    float a0=0.f, a1=0.f, a2=0.f, a3=0.f;
    for (int t = 0; t < 256; t += 4) {
        a0 += wv[t+0]*hp[(size_t)pm[t+0]*Dv + d];
        a1 += wv[t+1]*hp[(size_t)pm[t+1]*Dv + d];
        a2 += wv[t+2]*hp[(size_t)pm[t+2]*Dv + d];
        a3 += wv[t+3]*hp[(size_t)pm[t+3]*Dv + d];
    }
    g_segsum[(size_t)blk*Dv + d] = (a0 + a1) + (a2 + a3);
}

// ---------------------------------------------------------------
// K3c: emit ctx during the fused prefix walk (no PRE/SUF tables).
// Block = (bh, seg of 256 ranks); rows grouped by rank via g_loi sort.
// ---------------------------------------------------------------
__global__ __launch_bounds__(128) void k_emit() {
    __shared__ float wp[256], wn[256];
    __shared__ int pm[256];
    __shared__ uint32_t rloi[2048];
    __shared__ float rAn[2048], rBn[2048];
    __shared__ int sse[2];

    const int blk = blockIdx.x;
    const int seg = blk & 7;
    const int bh  = blk >> 3;
    const int d = threadIdx.x;
    const int n0 = seg * 256;
    const int b = bh >> 2, hh = bh & 3;

    for (int t = d; t < 256; t += 128) {
        wp[t] = g_sEp[bh*Sv + n0 + t];
        wn[t] = g_sEn[bh*Sv + n0 + t];
        pm[t] = g_perm[bh*Sv + n0 + t];
    }
    if (d < 2) {
        uint32_t thresh = (uint32_t)((d == 0 ? n0 : (seg == 7 ? 2049 : n0 + 256)) << 11);
        const uint32_t* L = g_loi + bh*Sv;
        int lo = 0, hi = Sv;
        while (lo < hi) {
            int mid = (lo + hi) >> 1;
            if (L[mid] < thresh) lo = mid + 1; else hi = mid;
        }
        sse[d] = lo;
    }
    __syncthreads();
    const int start = sse[0];
    const int nrows = sse[1] - start;
    for (int t = d; t < nrows; t += 128) {
        uint32_t v = g_loi[bh*Sv + start + t];
        rloi[t] = v;
        int i = (int)(v & 2047u);
        rAn[t] = g_An[bh*Sv + i];
        rBn[t] = g_Bn[bh*Sv + i];
    }
    __syncthreads();

    // per-d bases from dir-separated segsums (dir1=Ep, dir0=En)
    float basen = 0.f, basesuf = 0.f;
    const float totp = g_segsum[(size_t)((bh<<4) | (1<<3) | seg)*Dv + d];
    #pragma unroll
    for (int ss = 0; ss < 8; ss++) {
        if (ss < seg) basen   += g_segsum[(size_t)((bh<<4) | ss)*Dv + d];
        if (ss > seg) basesuf += g_segsum[(size_t)((bh<<4) | (1<<3) | ss)*Dv + d];
    }

    const float* hp = g_hp + (size_t)bh*Sv*Dv;
    float accp = 0.f, accn = 0.f;
    int ptr = 0;

    for (int tt = 0; tt < 256; tt += 8) {
        float vals[8];
        #pragma unroll
        for (int k = 0; k < 8; k++) vals[k] = hp[(size_t)pm[tt+k]*Dv + d];
        #pragma unroll
        for (int k = 0; k < 8; k++) {
            const uint32_t rank = (uint32_t)(n0 + tt + k);
            while (ptr < nrows && (rloi[ptr] >> 11) == rank) {
                float An = rAn[ptr], Bn = rBn[ptr];
                float v = An*(basesuf + (totp - accp)) + Bn*(basen + accn);
                float v2 = __shfl_down_sync(0xffffffffu, v, 1);
                if (!(d & 1)) {
                    int i = (int)(rloi[ptr] & 2047u);
                    size_t o = ((size_t)(b*Sv + i))*HDv + hh*Dv + d;
                    *(uint32_t*)(g_ctxb_hi + o) = pack_hi2(v, v2);
                    *(uint32_t*)(g_ctxb_lo + o) = pack_lo2(v, v2);
                }
                ptr++;
            }
            accp += wp[tt+k]*vals[k];
            accn += wn[tt+k]*vals[k];
        }
    }
    if (seg == 7) {
        while (ptr < nrows) {      // lo == 2048 rows: full prefix / empty suffix
            float An = rAn[ptr], Bn = rBn[ptr];
            float v = An*(basesuf + (totp - accp)) + Bn*(basen + accn);
            float v2 = __shfl_down_sync(0xffffffffu, v, 1);
            if (!(d & 1)) {
                int i = (int)(rloi[ptr] & 2047u);
                size_t o = ((size_t)(b*Sv + i))*HDv + hh*Dv + d;
                *(uint32_t*)(g_ctxb_hi + o) = pack_hi2(v, v2);
                *(uint32_t*)(g_ctxb_lo + o) = pack_lo2(v, v2);
            }
            ptr++;
        }
    }
}

// ---------------------------------------------------------------
// K3b: attn write — streaming stores, side stream
// ---------------------------------------------------------------
__global__ __launch_bounds__(256) void k_attnw(float* __restrict__ attn_out) {
    const int row = blockIdx.x;
    const int bh = row >> 11;
    const int tid = threadIdx.x;
    const float th = g_th[row], An = g_An[row], Bn = g_Bn[row];
    const float* e2b = g_e2  + bh*Sv;
    const float* epb = g_E2p + bh*Sv;
    const float* enb = g_E2n + bh*Sv;
    float* dst = attn_out + (size_t)row * Sv;
    #pragma unroll
    for (int t = 0; t < 2; t++) {
        int j = (tid + t*256) * 4;
        float4 e2v = *(const float4*)(e2b + j);
        float4 epv = *(const float4*)(epb + j);
        float4 env = *(const float4*)(enb + j);
        float4 p;
        p.x = (e2v.x > th) ? An*epv.x : Bn*env.x;
        p.y = (e2v.y > th) ? An*epv.y : Bn*env.y;
        p.z = (e2v.z > th) ? An*epv.z : Bn*env.z;
        p.w = (e2v.w > th) ? An*epv.w : Bn*env.w;
        __stcs((float4*)(dst + j), p);
    }
}

// ---------------------------------------------------------------
// K4: out = relu(ctx @ out_w^T + out_b) via bf16 3-split mma.sync.
// ---------------------------------------------------------------
#define G2_LDK 72
#define G2_AT (64*G2_LDK*2)
#define G2_BT (128*G2_LDK*2)
#define G2_BUF (2*G2_AT + 2*G2_BT)
#define G2_AH(q) ((uint32_t)((q)*G2_BUF))
#define G2_AL(q) ((uint32_t)((q)*G2_BUF + G2_AT))
#define G2_BH(q) ((uint32_t)((q)*G2_BUF + 2*G2_AT))
#define G2_BL(q) ((uint32_t)((q)*G2_BUF + 2*G2_AT + G2_BT))
#define G2_SMEM (2*G2_BUF)

__device__ __forceinline__ void g2_fill(int m0, int ch, uint32_t sb, int q, int tid) {
    const int k0 = ch * 64;
    #pragma unroll
    for (int t = 0; t < 4; t++) {
        int idx = tid + t*256;
        int p  = idx >> 9;
        int r  = (idx >> 3) & 63;
        int c8 = (idx & 7) * 8;
        const __nv_bfloat16* src = (p ? g_ctxb_lo : g_ctxb_hi)
            + (size_t)(m0 + r)*HDv + k0 + c8;
        CP16(sb + (p ? G2_AL(q) : G2_AH(q)) + (uint32_t)(r*G2_LDK + c8)*2, src);
    }
    #pragma unroll
    for (int t = 0; t < 8; t++) {
        int idx = tid + t*256;
        int p  = idx >> 10;
        int r  = (idx >> 3) & 127;
        int c8 = (idx & 7) * 8;
        const __nv_bfloat16* src = (p ? g_wb_lo : g_wb_hi)
            + (size_t)r*HDv + k0 + c8;
        CP16(sb + (p ? G2_BL(q) : G2_BH(q)) + (uint32_t)(r*G2_LDK + c8)*2, src);
    }
}

__global__ __launch_bounds__(256, 1) void k_gemm2t(const float* __restrict__ bias,
                                                   float* __restrict__ out) {
    const int m0 = blockIdx.x * 64;
    const int tid = threadIdx.x;
    const int w = tid >> 5, lane = tid & 31;
    const uint32_t sb = smem_u32(dynsmem);

    g2_fill(m0, 0, sb, 0, tid);
    CP_COMMIT();

    const int wm = w >> 2, wn = w & 3;
    const uint32_t arow = (uint32_t)((wm*32 + (lane & 15))*G2_LDK + (lane >> 4)*8) * 2;
    const uint32_t brow = (uint32_t)(((lane & 7) + ((lane >> 4) << 3))*G2_LDK
                                     + (((lane >> 3) & 1)*8)) * 2;
    float c[2][4][4] = {};

    #pragma unroll 1
    for (int ch = 0; ch < 8; ch++) {
        const int q = ch & 1;
        if (ch < 7) { g2_fill(m0, ch+1, sb, q^1, tid); CP_COMMIT(); CP_WAIT1(); }
        else        { CP_WAIT0(); }
        __syncthreads();

        #pragma unroll
        for (int ks = 0; ks < 4; ks++) {
            uint32_t bhf[2][4], blf[2][4];
            #pragma unroll
            for (int np = 0; np < 2; np++) {
                uint32_t bt = (uint32_t)((wn*32 + np*16)*G2_LDK)*2 + (uint32_t)(ks*16)*2;
                LDMX4(bhf[np][0],bhf[np][1],bhf[np][2],bhf[np][3], sb + G2_BH(q) + brow + bt);
                LDMX4(blf[np][0],blf[np][1],blf[np][2],blf[np][3], sb + G2_BL(q) + brow + bt);
            }
            #pragma unroll
            for (int mt = 0; mt < 2; mt++) {
                uint32_t at = (uint32_t)(mt*16*G2_LDK)*2 + (uint32_t)(ks*16)*2;
                uint32_t ah0,ah1,ah2,ah3, al0,al1,al2,al3;
                LDMX4(ah0,ah1,ah2,ah3, sb + G2_AH(q) + arow + at);
                LDMX4(al0,al1,al2,al3, sb + G2_AL(q) + arow + at);
                #pragma unroll
                for (int np = 0; np < 2; np++) {
                    MMA16816(c[mt][np*2],   ah0,ah1,ah2,ah3, bhf[np][0],bhf[np][1]);
                    MMA16816(c[mt][np*2],   al0,al1,al2,al3, bhf[np][0],bhf[np][1]);
                    MMA16816(c[mt][np*2],   ah0,ah1,ah2,ah3, blf[np][0],blf[np][1]);
                    MMA16816(c[mt][np*2+1], ah0,ah1,ah2,ah3, bhf[np][2],bhf[np][3]);
                    MMA16816(c[mt][np*2+1], al0,al1,al2,al3, bhf[np][2],bhf[np][3]);
                    MMA16816(c[mt][np*2+1], ah0,ah1,ah2,ah3, blf[np][2],blf[np][3]);
                }
            }
        }
        __syncthreads();
    }

    {
        const int g = lane >> 2, tg = lane & 3;
        #pragma unroll
        for (int mt = 0; mt < 2; mt++) {
            int r0 = m0 + wm*32 + mt*16 + g;
            #pragma unroll
            for (int nt = 0; nt < 4; nt++) {
                int n = wn*32 + nt*8 + tg*2;
                float b0 = bias[n], b1 = bias[n+1];
                float v0 = c[mt][nt][0] + b0, v1 = c[mt][nt][1] + b1;
                float v2 = c[mt][nt][2] + b0, v3 = c[mt][nt][3] + b1;
                *(float2*)(out + (size_t)r0*OUTv + n) =
                    make_float2(v0 > 0.f ? v0 : 0.f, v1 > 0.f ? v1 : 0.f);
                *(float2*)(out + (size_t)(r0+8)*OUTv + n) =
                    make_float2(v2 > 0.f ? v2 : 0.f, v3 > 0.f ? v3 : 0.f);
            }
        }
    }
}

// ---------------------------------------------------------------
extern "C" void kernel_launch(void* const* d_in, const int* in_sizes, int n_in,
                              void* d_out, int out_size) {
    const float* h     = (const float*)d_in[0];
    const void*  mask  = d_in[1];
    const float* W_w   = (const float*)d_in[2];
    const float* W_b   = (const float*)d_in[3];
    const float* a_w   = (const float*)d_in[4];
    const float* a_b   = (const float*)d_in[5];
    const float* out_w = (const float*)d_in[6];
    const float* out_b = (const float*)d_in[7];

    float* out  = (float*)d_out;
    float* attn = out + (size_t)Bv*Sv*OUTv;

    static int init_done = 0;
    static cudaStream_t s2;
    static cudaEvent_t evF0, evW, evF2, evJoin;
    if (!init_done) {
        cudaFuncSetAttribute(k_gemm1t, cudaFuncAttributeMaxDynamicSharedMemorySize, G1_SMEM);
        cudaFuncSetAttribute(k_prep,   cudaFuncAttributeMaxDynamicSharedMemorySize, PREP_SMEM);
        cudaFuncSetAttribute(k_gemm2t, cudaFuncAttributeMaxDynamicSharedMemorySize, G2_SMEM);
        cudaStreamCreateWithFlags(&s2, cudaStreamNonBlocking);
        cudaEventCreateWithFlags(&evF0,   cudaEventDisableTiming);
        cudaEventCreateWithFlags(&evW,    cudaEventDisableTiming);
        cudaEventCreateWithFlags(&evF2,   cudaEventDisableTiming);
        cudaEventCreateWithFlags(&evJoin, cudaEventDisableTiming);
        init_done = 1;
    }

    // fork 0: out_w conversion overlaps mask + gemm1t
    cudaEventRecord(evF0, 0);
    cudaStreamWaitEvent(s2, evF0, 0);
    k_wcvt  <<<64, 256, 0, s2>>>(out_w);
    cudaEventRecord(evW, s2);

    k_mask  <<<1, 256>>>(mask);
    k_gemm1t<<<dim3(64, 4), 512, G1_SMEM>>>(h, W_w, W_b, a_w);
    k_prep  <<<BHv, 1024, PREP_SMEM>>>(a_b);

    // fork 2: attn write overlaps scan/emit/gemm2 branch
    cudaEventRecord(evF2, 0);
    cudaStreamWaitEvent(s2, evF2, 0);
    k_attnw <<<NSv, 256, 0, s2>>>(attn);
    cudaEventRecord(evJoin, s2);

    k_scan1 <<<256, 128>>>();
    k_emit  <<<BHv*8, 128>>>();
    cudaStreamWaitEvent(0, evW, 0);      // gemm2t needs wcvt only
    k_gemm2t<<<128, 256, G2_SMEM>>>(out_b, out);

    cudaStreamWaitEvent(0, evJoin, 0);   // join attnw
}

// round 17
// speedup vs baseline: 1.9049x; 1.9049x over previous
#include <cuda_runtime.h>
#include <cuda_bf16.h>
#include <math.h>
#include <stdint.h>

#define Bv 4
#define Sv 2048
#define Fv 128
#define Hv 4
#define Dv 128
#define HDv 512
#define OUTv 128
#define BHv 16
#define NSv (BHv*Sv)
#define NEG 0.01f

// ---- device scratch ----
__device__ float g_hp[NSv*Dv];          // fp32 [bh][s][d]
__device__ float g_e1[NSv];
__device__ float g_e2[NSv];
__device__ float g_An[NSv];
__device__ float g_Bn[NSv];
__device__ float g_th[NSv];
__device__ float g_E2p[NSv];
__device__ float g_E2n[NSv];
__device__ int   g_lo[NSv];
__device__ int   g_perm[NSv];
__device__ float g_sEp[NSv];
__device__ float g_sEn[NSv];
__device__ int   g_masked[Bv*Sv];
__device__ float g_pre[BHv*2049*Dv];
__device__ float g_suf[BHv*2049*Dv];
__device__ float g_segsum[BHv*2*8*Dv];
__device__ __nv_bfloat16 g_ctxb_hi[Bv*Sv*HDv];
__device__ __nv_bfloat16 g_ctxb_lo[Bv*Sv*HDv];
__device__ __nv_bfloat16 g_wb_hi[OUTv*HDv];
__device__ __nv_bfloat16 g_wb_lo[OUTv*HDv];

__device__ __forceinline__ uint32_t smem_u32(const void* p) {
    uint32_t a;
    asm("{ .reg .u64 t; cvta.to.shared.u64 t, %1; cvt.u32.u64 %0, t; }" : "=r"(a) : "l"(p));
    return a;
}
#define LDMX4(r0,r1,r2,r3,addr) \
    asm volatile("ldmatrix.sync.aligned.m8n8.x4.shared.b16 {%0,%1,%2,%3}, [%4];" \
        : "=r"(r0),"=r"(r1),"=r"(r2),"=r"(r3) : "r"(addr))
#define MMA16816(c,a0,a1,a2,a3,b0,b1) \
    asm volatile("mma.sync.aligned.m16n8k16.row.col.f32.bf16.bf16.f32 " \
        "{%0,%1,%2,%3}, {%4,%5,%6,%7}, {%8,%9}, {%0,%1,%2,%3};" \
        : "+f"((c)[0]),"+f"((c)[1]),"+f"((c)[2]),"+f"((c)[3]) \
        : "r"(a0),"r"(a1),"r"(a2),"r"(a3), "r"(b0),"r"(b1))
#define CP16(dst, src) \
    asm volatile("cp.async.cg.shared.global [%0], [%1], 16;" :: "r"(dst), "l"(src) : "memory")
#define CP_COMMIT() asm volatile("cp.async.commit_group;" ::: "memory")
#define CP_WAIT1()  asm volatile("cp.async.wait_group 1;" ::: "memory")
#define CP_WAIT0()  asm volatile("cp.async.wait_group 0;" ::: "memory")

__device__ __forceinline__ uint32_t pack_hi2(float a, float b) {
    __nv_bfloat16 ha = __float2bfloat16_rn(a), hb = __float2bfloat16_rn(b);
    return ((uint32_t)__bfloat16_as_ushort(hb) << 16) | __bfloat16_as_ushort(ha);
}
__device__ __forceinline__ uint32_t pack_lo2(float a, float b) {
    __nv_bfloat16 ha = __float2bfloat16_rn(a), hb = __float2bfloat16_rn(b);
    float ra = a - __bfloat162float(ha), rb = b - __bfloat162float(hb);
    __nv_bfloat16 la = __float2bfloat16_rn(ra), lb = __float2bfloat16_rn(rb);
    return ((uint32_t)__bfloat16_as_ushort(lb) << 16) | __bfloat16_as_ushort(la);
}

extern __shared__ __align__(128) unsigned char dynsmem[];

// ---------------------------------------------------------------
// K0: decode mask buffer
// ---------------------------------------------------------------
__global__ void k_mask(const void* mraw) {
    __shared__ int ssum[256];
    __shared__ int fmt;
    const unsigned char* mb = (const unsigned char*)mraw;
    int tid = threadIdx.x;
    int s = 0;
    for (int i = tid; i < Bv*Sv; i += 256) s += mb[i];
    ssum[tid] = s;
    __syncthreads();
    for (int st = 128; st > 0; st >>= 1) {
        if (tid < st) ssum[tid] += ssum[tid + st];
        __syncthreads();
    }
    if (tid == 0) fmt = (ssum[0] > (Bv*Sv*5/16)) ? 1 : 0;
    __syncthreads();
    if (fmt) {
        for (int i = tid; i < Bv*Sv; i += 256) g_masked[i] = (mb[i] != 0);
    } else {
        const int* mi = (const int*)mraw;
        for (int i = tid; i < Bv*Sv; i += 256) g_masked[i] = (mi[i] != 0);
    }
}

// ---------------------------------------------------------------
// K0b: convert out_w to bf16 hi/lo (side stream)
// ---------------------------------------------------------------
__global__ void k_wcvt(const float* __restrict__ W) {
    int i = blockIdx.x * 256 + threadIdx.x;
    float4 v = *(const float4*)(W + (size_t)i*4);
    *(uint2*)(g_wb_hi + (size_t)i*4) = make_uint2(pack_hi2(v.x,v.y), pack_hi2(v.z,v.w));
    *(uint2*)(g_wb_lo + (size_t)i*4) = make_uint2(pack_lo2(v.x,v.y), pack_lo2(v.z,v.w));
}

// ---------------------------------------------------------------
// K1: hp = h @ W_w^T + W_b via bf16 3-split mma.sync, fused e1/e2.
// K-halved pipelined prologue (R15 form).
// ---------------------------------------------------------------
#define G1_LDK 136
#define G1_T  (128*G1_LDK*2)
#define G1_AH 0u
#define G1_AL ((uint32_t)G1_T)
#define G1_BH ((uint32_t)(2*G1_T))
#define G1_BL ((uint32_t)(3*G1_T))
#define G1_RED ((uint32_t)(4*G1_T))
#define G1_SA  ((uint32_t)(4*G1_T + 4096))
#define G1_SMEM (4*G1_T + 4096 + 1024)

__device__ __forceinline__ void g1_convert_half(const float* __restrict__ A,
                                                const float* __restrict__ W,
                                                int m0, int n0, int half, int tid) {
    const int cbase = half * 64;
    #pragma unroll
    for (int t = 0; t < 4; t++) {
        int idx = tid + t*512;
        int r = idx >> 4, c4 = ((idx & 15) << 2) + cbase;
        float4 v = *(const float4*)(A + (size_t)(m0+r)*Fv + c4);
        uint32_t boff = (uint32_t)(r*G1_LDK + c4) * 2;
        *(uint2*)(dynsmem + G1_AH + boff) = make_uint2(pack_hi2(v.x,v.y), pack_hi2(v.z,v.w));
        *(uint2*)(dynsmem + G1_AL + boff) = make_uint2(pack_lo2(v.x,v.y), pack_lo2(v.z,v.w));
    }
    #pragma unroll
    for (int t = 0; t < 4; t++) {
        int idx = tid + t*512;
        int r = idx >> 4, c4 = ((idx & 15) << 2) + cbase;
        float4 v = *(const float4*)(W + (size_t)(n0+r)*Fv + c4);
        uint32_t boff = (uint32_t)(r*G1_LDK + c4) * 2;
        *(uint2*)(dynsmem + G1_BH + boff) = make_uint2(pack_hi2(v.x,v.y), pack_hi2(v.z,v.w));
        *(uint2*)(dynsmem + G1_BL + boff) = make_uint2(pack_lo2(v.x,v.y), pack_lo2(v.z,v.w));
    }
}

__global__ __launch_bounds__(512, 1) void k_gemm1t(const float* __restrict__ A,
                                                   const float* __restrict__ W,
                                                   const float* __restrict__ bias,
                                                   const float* __restrict__ aw) {
    const int m0 = blockIdx.x * 128;
    const int n0 = blockIdx.y * 128;
    const int tid = threadIdx.x;
    const int w = tid >> 5, lane = tid & 31;
    const uint32_t sb = smem_u32(dynsmem);

    if (tid < 256) ((float*)(dynsmem + G1_SA))[tid] = aw[tid];

    g1_convert_half(A, W, m0, n0, 0, tid);
    __syncthreads();

    const int wm = w >> 2, wn = w & 3;
    const uint32_t arow = (uint32_t)((wm*32 + (lane & 15))*G1_LDK + (lane >> 4)*8) * 2;
    const uint32_t brow = (uint32_t)(((lane & 7) + ((lane >> 4) << 3))*G1_LDK
                                     + (((lane >> 3) & 1)*8)) * 2;
    float c[2][4][4] = {};

    #pragma unroll
    for (int half = 0; half < 2; half++) {
        if (half == 0) g1_convert_half(A, W, m0, n0, 1, tid);
        #pragma unroll
        for (int ks = half*4; ks < half*4 + 4; ks++) {
            uint32_t bhf[2][4], blf[2][4];
            #pragma unroll
            for (int np = 0; np < 2; np++) {
                uint32_t bt = (uint32_t)((wn*32 + np*16)*G1_LDK)*2 + (uint32_t)(ks*16)*2;
                LDMX4(bhf[np][0],bhf[np][1],bhf[np][2],bhf[np][3], sb + G1_BH + brow + bt);
                LDMX4(blf[np][0],blf[np][1],blf[np][2],blf[np][3], sb + G1_BL + brow + bt);
            }
            #pragma unroll
            for (int mt = 0; mt < 2; mt++) {
                uint32_t at = (uint32_t)(mt*16*G1_LDK)*2 + (uint32_t)(ks*16)*2;
                uint32_t ah0,ah1,ah2,ah3, al0,al1,al2,al3;
                LDMX4(ah0,ah1,ah2,ah3, sb + G1_AH + arow + at);
                LDMX4(al0,al1,al2,al3, sb + G1_AL + arow + at);
                #pragma unroll
                for (int np = 0; np < 2; np++) {
                    MMA16816(c[mt][np*2],   ah0,ah1,ah2,ah3, bhf[np][0],bhf[np][1]);
                    MMA16816(c[mt][np*2],   al0,al1,al2,al3, bhf[np][0],bhf[np][1]);
                    MMA16816(c[mt][np*2],   ah0,ah1,ah2,ah3, blf[np][0],blf[np][1]);
                    MMA16816(c[mt][np*2+1], ah0,ah1,ah2,ah3, bhf[np][2],bhf[np][3]);
                    MMA16816(c[mt][np*2+1], al0,al1,al2,al3, bhf[np][2],bhf[np][3]);
                    MMA16816(c[mt][np*2+1], ah0,ah1,ah2,ah3, blf[np][2],blf[np][3]);
                }
            }
        }
        if (half == 0) __syncthreads();
    }

    const int bb = m0 >> 11, s0 = m0 & (Sv-1), hh = n0 >> 7;
    const int bh = bb*Hv + hh;
    const int g = lane >> 2, tg = lane & 3;
    float* red = (float*)(dynsmem + G1_RED);
    const float* sa1 = (const float*)(dynsmem + G1_SA);
    const float* sa2 = sa1 + 128;

    float pe1[2][2] = {}, pe2[2][2] = {};
    #pragma unroll
    for (int mt = 0; mt < 2; mt++) {
        #pragma unroll
        for (int nt = 0; nt < 4; nt++) {
            int d = wn*32 + nt*8 + tg*2;
            float b0 = bias[n0 + d], b1 = bias[n0 + d + 1];
            float a10 = sa1[d], a11 = sa1[d+1];
            float a20 = sa2[d], a21 = sa2[d+1];
            #pragma unroll
            for (int half = 0; half < 2; half++) {
                int r = wm*32 + mt*16 + half*8 + g;
                float v0 = c[mt][nt][half*2]   + b0;
                float v1 = c[mt][nt][half*2+1] + b1;
                *(float2*)(g_hp + ((size_t)bh*Sv + s0 + r)*Dv + d) = make_float2(v0, v1);
                pe1[mt][half] += v0*a10 + v1*a11;
                pe2[mt][half] += v0*a20 + v1*a21;
            }
        }
    }
    #pragma unroll
    for (int mt = 0; mt < 2; mt++) {
        #pragma unroll
        for (int half = 0; half < 2; half++) {
            float e1 = pe1[mt][half], e2 = pe2[mt][half];
            e1 += __shfl_xor_sync(0xffffffffu, e1, 1);
            e1 += __shfl_xor_sync(0xffffffffu, e1, 2);
            e2 += __shfl_xor_sync(0xffffffffu, e2, 1);
            e2 += __shfl_xor_sync(0xffffffffu, e2, 2);
            if (tg == 0) {
                int r = wm*32 + mt*16 + half*8 + g;
                red[(r*4 + wn)*2 + 0] = e1;
                red[(r*4 + wn)*2 + 1] = e2;
            }
        }
    }
    __syncthreads();
    if (tid < 128) {
        int r = tid;
        float e1 = red[(r*4+0)*2] + red[(r*4+1)*2] + red[(r*4+2)*2] + red[(r*4+3)*2];
        float e2 = red[(r*4+0)*2+1] + red[(r*4+1)*2+1] + red[(r*4+2)*2+1] + red[(r*4+3)*2+1];
        int s = s0 + r;
        int row = bh*Sv + s;
        g_e1[row] = e1;
        g_e2[row] = e2;
        int msk = g_masked[bb*Sv + s];
        g_E2p[row] = msk ? 0.f : expf(e2);
        g_E2n[row] = msk ? 0.f : expf(NEG*e2);
    }
}

// ---------------------------------------------------------------
// K2: per (b,h) softmax prep. 32-bit packed-key bitonic sort (R13/R15 form).
// ---------------------------------------------------------------
#define P_SKEY 0u
#define P_KEYF 16384u
#define P_V1   24576u
#define P_V2   32768u
#define P_PREN 40960u
#define P_SUFP 49408u
#define P_CH1  57856u
#define P_CH2  58112u
#define PREP_SMEM 58880

__device__ __forceinline__ uint32_t f2sort(float f) {
    uint32_t u = __float_as_uint(f);
    return (u & 0x80000000u) ? ~u : (u | 0x80000000u);
}
__device__ __forceinline__ uint32_t bsel32(uint32_t a, uint32_t p, bool up, bool lower) {
    uint32_t mn = a < p ? a : p;
    uint32_t mx = a < p ? p : a;
    return (up == lower) ? mn : mx;
}

__global__ __launch_bounds__(1024) void k_prep(const float* __restrict__ ab_p) {
    uint32_t* skey = (uint32_t*)(dynsmem + P_SKEY);
    float* keyf = (float*)(dynsmem + P_KEYF);
    float* v1   = (float*)(dynsmem + P_V1);
    float* v2   = (float*)(dynsmem + P_V2);
    float* pren = (float*)(dynsmem + P_PREN);
    float* sufp = (float*)(dynsmem + P_SUFP);
    float* ch1  = (float*)(dynsmem + P_CH1);
    float* ch2  = (float*)(dynsmem + P_CH2);

    const int bh = blockIdx.x;
    const int b  = bh >> 2;
    const int tid = threadIdx.x;
    const float ab = ab_p[0];

    uint32_t r0, r1;
    {
        int j0 = 2*tid, j1 = 2*tid + 1;
        float e20 = g_e2[bh*Sv + j0], e21 = g_e2[bh*Sv + j1];
        float k0 = g_masked[b*Sv + j0] ? -1e30f : e20;
        float k1 = g_masked[b*Sv + j1] ? -1e30f : e21;
        r0 = (f2sort(k0) & 0xFFFFF800u) | (uint32_t)j0;
        r1 = (f2sort(k1) & 0xFFFFF800u) | (uint32_t)j1;
    }

    for (int k = 2; k <= Sv; k <<= 1) {
        const bool up = (((2*tid) & k) == 0);
        for (int j = k >> 1; j > 0; j >>= 1) {
            if (j == 1) {
                if ((r0 > r1) == up) { uint32_t t = r0; r0 = r1; r1 = t; }
            } else if (j <= 32) {
                int m = j >> 1;
                uint32_t p0 = __shfl_xor_sync(0xffffffffu, r0, m);
                uint32_t p1 = __shfl_xor_sync(0xffffffffu, r1, m);
                bool lower = ((tid & m) == 0);
                r0 = bsel32(r0, p0, up, lower);
                r1 = bsel32(r1, p1, up, lower);
            } else {
                __syncthreads();
                skey[2*tid] = r0; skey[2*tid+1] = r1;
                __syncthreads();
                int pt = tid ^ (j >> 1);
                uint32_t p0 = skey[2*pt];
                uint32_t p1 = skey[2*pt+1];
                bool lower = ((tid & (j >> 1)) == 0);
                r0 = bsel32(r0, p0, up, lower);
                r1 = bsel32(r1, p1, up, lower);
            }
        }
    }
    __syncthreads();
    skey[2*tid] = r0; skey[2*tid+1] = r1;
    __syncthreads();

    for (int n = tid; n < Sv; n += 1024) {
        int jj = (int)(skey[n] & 2047u);
        int msk = g_masked[b*Sv + jj];
        float kf = msk ? -1e30f : g_e2[bh*Sv + jj];
        float ep = expf(kf), en = expf(NEG*kf);
        keyf[n] = kf; v1[n] = ep; v2[n] = en;
        g_perm[bh*Sv + n] = jj;
        g_sEp[bh*Sv + n] = ep;
        g_sEn[bh*Sv + n] = en;
    }
    __syncthreads();

    const float M2 = keyf[Sv-1];

    if (tid < 64) {
        int base = tid * 32;
        float s1 = 0.f, s2 = 0.f;
        for (int t = 0; t < 32; t++) { s1 += v1[base+t]; s2 += v2[base+t]; }
        ch1[tid] = s1; ch2[tid] = s2;
    }
    __syncthreads();
    if (tid == 0) {
        float r = 0.f;
        for (int c = 0; c < 64; c++) { float t = ch2[c]; ch2[c] = r; r += t; }
        pren[Sv] = r;
        r = 0.f;
        for (int c = 63; c >= 0; c--) { float t = ch1[c]; ch1[c] = r; r += t; }
    }
    __syncthreads();
    if (tid < 64) {
        int base = tid * 32;
        float run = ch2[tid];
        for (int t = 0; t < 32; t++) { pren[base+t] = run; run += v2[base+t]; }
        float runs = ch1[tid];
        for (int t = 31; t >= 0; t--) { runs += v1[base+t]; sufp[base+t] = runs; }
    }
    if (tid == 0) sufp[Sv] = 0.f;
    __syncthreads();

    for (int i = tid; i < Sv; i += 1024) {
        float e1 = g_e1[bh*Sv + i];
        float eb = e1 + ab;
        float pre = eb + M2;
        float m = (pre > 0.f) ? pre : NEG*pre;
        float th = -eb;
        float A  = expf(eb - m);
        float Bc = expf(NEG*eb - m);
        int lo = 0, hi = Sv;
        while (lo < hi) {
            int mid = (lo + hi) >> 1;
            if (keyf[mid] <= th) lo = mid + 1; else hi = mid;
        }
        float rowsum = A*sufp[lo] + Bc*pren[lo];
        float inv = 1.0f / rowsum;
        g_An[bh*Sv + i] = A * inv;
        g_Bn[bh*Sv + i] = Bc * inv;
        g_th[bh*Sv + i] = th;
        g_lo[bh*Sv + i] = lo;
    }
}

// ---------------------------------------------------------------
// K3a-1: segment sums (dir-separated, R13 form)
// ---------------------------------------------------------------
__global__ __launch_bounds__(128) void k_scan1() {
    __shared__ float wv[256];
    __shared__ int pm[256];
    const int blk = blockIdx.x;
    const int seg = blk & 7;
    const int dir = (blk >> 3) & 1;
    const int bh  = blk >> 4;
    const int d = threadIdx.x;
    const int n0 = seg * 256;
    const float* src = dir ? (g_sEp + bh*Sv) : (g_sEn + bh*Sv);
    for (int t = d; t < 256; t += 128) {
        wv[t] = src[n0 + t];
        pm[t] = g_perm[bh*Sv + n0 + t];
    }
    __syncthreads();
    const float* hp = g_hp + (size_t)bh*Sv*Dv;
    float a0=0.f, a1=0.f, a2=0.f, a3=0.f;
    for (int t = 0; t < 256; t += 4) {
        a0 += wv[t+0]*hp[(size_t)pm[t+0]*Dv + d];
        a1 += wv[t+1]*hp[(size_t)pm[t+1]*Dv + d];
        a2 += wv[t+2]*hp[(size_t)pm[t+2]*Dv + d];
        a3 += wv[t+3]*hp[(size_t)pm[t+3]*Dv + d];
    }
    g_segsum[(size_t)blk*Dv + d] = (a0 + a1) + (a2 + a3);
}

// ---------------------------------------------------------------
// K3a-2: local scan -> PRE/SUF (R13 form, streaming table stores)
// ---------------------------------------------------------------
__global__ __launch_bounds__(128) void k_scan2() {
    __shared__ float wv[256];
    __shared__ int pm[256];
    const int blk = blockIdx.x;
    const int seg = blk & 7;
    const int dir = (blk >> 3) & 1;
    const int bh  = blk >> 4;
    const int d = threadIdx.x;
    const int n0 = seg * 256;
    const float* src = dir ? (g_sEp + bh*Sv) : (g_sEn + bh*Sv);
    for (int t = d; t < 256; t += 128) {
        wv[t] = src[n0 + t];
        pm[t] = g_perm[bh*Sv + n0 + t];
    }
    __syncthreads();
    const float* hp = g_hp + (size_t)bh*Sv*Dv;
    const int base = (bh*2 + dir) * 8;
    float acc = 0.f;
    if (dir == 0) {
        for (int ss = 0; ss < seg; ss++) acc += g_segsum[(size_t)(base+ss)*Dv + d];
        float* pre = g_pre + (size_t)bh*2049*Dv;
        for (int t = 0; t < 256; t += 8) {
            float vals[8];
            #pragma unroll
            for (int k = 0; k < 8; k++) vals[k] = hp[(size_t)pm[t+k]*Dv + d];
            #pragma unroll
            for (int k = 0; k < 8; k++) {
                __stcs(pre + (size_t)(n0+t+k)*Dv + d, acc);
                acc += wv[t+k]*vals[k];
            }
        }
        if (seg == 7) __stcs(pre + (size_t)Sv*Dv + d, acc);
    } else {
        for (int ss = seg+1; ss < 8; ss++) acc += g_segsum[(size_t)(base+ss)*Dv + d];
        float* suf = g_suf + (size_t)bh*2049*Dv;
        if (seg == 7) __stcs(suf + (size_t)Sv*Dv + d, 0.f);
        for (int t = 248; t >= 0; t -= 8) {
            float vals[8];
            #pragma unroll
            for (int k = 7; k >= 0; k--) vals[k] = hp[(size_t)pm[t+k]*Dv + d];
            #pragma unroll
            for (int k = 7; k >= 0; k--) {
                acc += wv[t+k]*vals[k];
                __stcs(suf + (size_t)(n0+t+k)*Dv + d, acc);
            }
        }
    }
}

// ---------------------------------------------------------------
// K3b: attn write — streaming stores, side stream
// ---------------------------------------------------------------
__global__ __launch_bounds__(256) void k_attnw(float* __restrict__ attn_out) {
    const int row = blockIdx.x;
    const int bh = row >> 11;
    const int tid = threadIdx.x;
    const float th = g_th[row], An = g_An[row], Bn = g_Bn[row];
    const float* e2b = g_e2  + bh*Sv;
    const float* epb = g_E2p + bh*Sv;
    const float* enb = g_E2n + bh*Sv;
    float* dst = attn_out + (size_t)row * Sv;
    #pragma unroll
    for (int t = 0; t < 2; t++) {
        int j = (tid + t*256) * 4;
        float4 e2v = *(const float4*)(e2b + j);
        float4 epv = *(const float4*)(epb + j);
        float4 env = *(const float4*)(enb + j);
        float4 p;
        p.x = (e2v.x > th) ? An*epv.x : Bn*env.x;
        p.y = (e2v.y > th) ? An*epv.y : Bn*env.y;
        p.z = (e2v.z > th) ? An*epv.z : Bn*env.z;
        p.w = (e2v.w > th) ? An*epv.w : Bn*env.w;
        __stcs((float4*)(dst + j), p);
    }
}

// ---------------------------------------------------------------
// K3c: ctx gather -> bf16 hi/lo
// ---------------------------------------------------------------
__global__ __launch_bounds__(256) void k_gather() {
    const int row = blockIdx.x * 8 + (threadIdx.x >> 5);
    const int lane = threadIdx.x & 31;
    const int bh = row >> 11, i = row & (Sv-1);
    const int b = bh >> 2, hh = bh & 3;
    const int lo = g_lo[row];
    const float An = g_An[row], Bn = g_Bn[row];
    float4 sv = *(const float4*)(g_suf + ((size_t)bh*2049 + lo)*Dv + lane*4);
    float4 pv = *(const float4*)(g_pre + ((size_t)bh*2049 + lo)*Dv + lane*4);
    float x = An*sv.x + Bn*pv.x;
    float y = An*sv.y + Bn*pv.y;
    float z = An*sv.z + Bn*pv.z;
    float ww = An*sv.w + Bn*pv.w;
    size_t o = ((size_t)(b*Sv + i))*HDv + hh*Dv + lane*4;
    *(uint2*)(g_ctxb_hi + o) = make_uint2(pack_hi2(x,y), pack_hi2(z,ww));
    *(uint2*)(g_ctxb_lo + o) = make_uint2(pack_lo2(x,y), pack_lo2(z,ww));
}

// ---------------------------------------------------------------
// K4: out = relu(ctx @ out_w^T + out_b) via bf16 3-split mma.sync.
// ---------------------------------------------------------------
#define G2_LDK 72
#define G2_AT (64*G2_LDK*2)
#define G2_BT (128*G2_LDK*2)
#define G2_BUF (2*G2_AT + 2*G2_BT)
#define G2_AH(q) ((uint32_t)((q)*G2_BUF))
#define G2_AL(q) ((uint32_t)((q)*G2_BUF + G2_AT))
#define G2_BH(q) ((uint32_t)((q)*G2_BUF + 2*G2_AT))
#define G2_BL(q) ((uint32_t)((q)*G2_BUF + 2*G2_AT + G2_BT))
#define G2_SMEM (2*G2_BUF)

__device__ __forceinline__ void g2_fill(int m0, int ch, uint32_t sb, int q, int tid) {
    const int k0 = ch * 64;
    #pragma unroll
    for (int t = 0; t < 4; t++) {
        int idx = tid + t*256;
        int p  = idx >> 9;
        int r  = (idx >> 3) & 63;
        int c8 = (idx & 7) * 8;
        const __nv_bfloat16* src = (p ? g_ctxb_lo : g_ctxb_hi)
            + (size_t)(m0 + r)*HDv + k0 + c8;
        CP16(sb + (p ? G2_AL(q) : G2_AH(q)) + (uint32_t)(r*G2_LDK + c8)*2, src);
    }
    #pragma unroll
    for (int t = 0; t < 8; t++) {
        int idx = tid + t*256;
        int p  = idx >> 10;
        int r  = (idx >> 3) & 127;
        int c8 = (idx & 7) * 8;
        const __nv_bfloat16* src = (p ? g_wb_lo : g_wb_hi)
            + (size_t)r*HDv + k0 + c8;
        CP16(sb + (p ? G2_BL(q) : G2_BH(q)) + (uint32_t)(r*G2_LDK + c8)*2, src);
    }
}

__global__ __launch_bounds__(256, 1) void k_gemm2t(const float* __restrict__ bias,
                                                   float* __restrict__ out) {
    const int m0 = blockIdx.x * 64;
    const int tid = threadIdx.x;
    const int w = tid >> 5, lane = tid & 31;
    const uint32_t sb = smem_u32(dynsmem);

    g2_fill(m0, 0, sb, 0, tid);
    CP_COMMIT();

    const int wm = w >> 2, wn = w & 3;
    const uint32_t arow = (uint32_t)((wm*32 + (lane & 15))*G2_LDK + (lane >> 4)*8) * 2;
    const uint32_t brow = (uint32_t)(((lane & 7) + ((lane >> 4) << 3))*G2_LDK
                                     + (((lane >> 3) & 1)*8)) * 2;
    float c[2][4][4] = {};

    #pragma unroll 1
    for (int ch = 0; ch < 8; ch++) {
        const int q = ch & 1;
        if (ch < 7) { g2_fill(m0, ch+1, sb, q^1, tid); CP_COMMIT(); CP_WAIT1(); }
        else        { CP_WAIT0(); }
        __syncthreads();

        #pragma unroll
        for (int ks = 0; ks < 4; ks++) {
            uint32_t bhf[2][4], blf[2][4];
            #pragma unroll
            for (int np = 0; np < 2; np++) {
                uint32_t bt = (uint32_t)((wn*32 + np*16)*G2_LDK)*2 + (uint32_t)(ks*16)*2;
                LDMX4(bhf[np][0],bhf[np][1],bhf[np][2],bhf[np][3], sb + G2_BH(q) + brow + bt);
                LDMX4(blf[np][0],blf[np][1],blf[np][2],blf[np][3], sb + G2_BL(q) + brow + bt);
            }
            #pragma unroll
            for (int mt = 0; mt < 2; mt++) {
                uint32_t at = (uint32_t)(mt*16*G2_LDK)*2 + (uint32_t)(ks*16)*2;
                uint32_t ah0,ah1,ah2,ah3, al0,al1,al2,al3;
                LDMX4(ah0,ah1,ah2,ah3, sb + G2_AH(q) + arow + at);
                LDMX4(al0,al1,al2,al3, sb + G2_AL(q) + arow + at);
                #pragma unroll
                for (int np = 0; np < 2; np++) {
                    MMA16816(c[mt][np*2],   ah0,ah1,ah2,ah3, bhf[np][0],bhf[np][1]);
                    MMA16816(c[mt][np*2],   al0,al1,al2,al3, bhf[np][0],bhf[np][1]);
                    MMA16816(c[mt][np*2],   ah0,ah1,ah2,ah3, blf[np][0],blf[np][1]);
                    MMA16816(c[mt][np*2+1], ah0,ah1,ah2,ah3, bhf[np][2],bhf[np][3]);
                    MMA16816(c[mt][np*2+1], al0,al1,al2,al3, bhf[np][2],bhf[np][3]);
                    MMA16816(c[mt][np*2+1], ah0,ah1,ah2,ah3, blf[np][2],blf[np][3]);
                }
            }
        }
        __syncthreads();
    }

    {
        const int g = lane >> 2, tg = lane & 3;
        #pragma unroll
        for (int mt = 0; mt < 2; mt++) {
            int r0 = m0 + wm*32 + mt*16 + g;
            #pragma unroll
            for (int nt = 0; nt < 4; nt++) {
                int n = wn*32 + nt*8 + tg*2;
                float b0 = bias[n], b1 = bias[n+1];
                float v0 = c[mt][nt][0] + b0, v1 = c[mt][nt][1] + b1;
                float v2 = c[mt][nt][2] + b0, v3 = c[mt][nt][3] + b1;
                *(float2*)(out + (size_t)r0*OUTv + n) =
                    make_float2(v0 > 0.f ? v0 : 0.f, v1 > 0.f ? v1 : 0.f);
                *(float2*)(out + (size_t)(r0+8)*OUTv + n) =
                    make_float2(v2 > 0.f ? v2 : 0.f, v3 > 0.f ? v3 : 0.f);
            }
        }
    }
}

// ---------------------------------------------------------------
extern "C" void kernel_launch(void* const* d_in, const int* in_sizes, int n_in,
                              void* d_out, int out_size) {
    const float* h     = (const float*)d_in[0];
    const void*  mask  = d_in[1];
    const float* W_w   = (const float*)d_in[2];
    const float* W_b   = (const float*)d_in[3];
    const float* a_w   = (const float*)d_in[4];
    const float* a_b   = (const float*)d_in[5];
    const float* out_w = (const float*)d_in[6];
    const float* out_b = (const float*)d_in[7];

    float* out  = (float*)d_out;
    float* attn = out + (size_t)Bv*Sv*OUTv;

    static int init_done = 0;
    static cudaStream_t s2;
    static cudaEvent_t evF0, evW, evF2, evJoin;
    if (!init_done) {
        cudaFuncSetAttribute(k_gemm1t, cudaFuncAttributeMaxDynamicSharedMemorySize, G1_SMEM);
        cudaFuncSetAttribute(k_prep,   cudaFuncAttributeMaxDynamicSharedMemorySize, PREP_SMEM);
        cudaFuncSetAttribute(k_gemm2t, cudaFuncAttributeMaxDynamicSharedMemorySize, G2_SMEM);
        cudaStreamCreateWithFlags(&s2, cudaStreamNonBlocking);
        cudaEventCreateWithFlags(&evF0,   cudaEventDisableTiming);
        cudaEventCreateWithFlags(&evW,    cudaEventDisableTiming);
        cudaEventCreateWithFlags(&evF2,   cudaEventDisableTiming);
        cudaEventCreateWithFlags(&evJoin, cudaEventDisableTiming);
        init_done = 1;
    }

    // fork 0: out_w conversion overlaps mask + gemm1t
    cudaEventRecord(evF0, 0);
    cudaStreamWaitEvent(s2, evF0, 0);
    k_wcvt  <<<64, 256, 0, s2>>>(out_w);
    cudaEventRecord(evW, s2);

    k_mask  <<<1, 256>>>(mask);
    k_gemm1t<<<dim3(64, 4), 512, G1_SMEM>>>(h, W_w, W_b, a_w);
    k_prep  <<<BHv, 1024, PREP_SMEM>>>(a_b);

    // fork 2: attn write overlaps scan/gather/gemm2 branch
    cudaEventRecord(evF2, 0);
    cudaStreamWaitEvent(s2, evF2, 0);
    k_attnw <<<NSv, 256, 0, s2>>>(attn);
    cudaEventRecord(evJoin, s2);

    k_scan1 <<<256, 128>>>();
    k_scan2 <<<256, 128>>>();
    k_gather<<<NSv/8, 256>>>();
    cudaStreamWaitEvent(0, evW, 0);      // gemm2t needs wcvt only
    k_gemm2t<<<128, 256, G2_SMEM>>>(out_b, out);

    cudaStreamWaitEvent(0, evJoin, 0);   // join attnw
}